// round 5
// baseline (speedup 1.0000x reference)
#include <cuda_runtime.h>
#include <cstdint>

// NGP hash-grid interpolation encoding.
// B=262144 points (x in [0,1)^3), L=16 levels, T=19 (2^19-entry tables), F=2.

constexpr int      LVL    = 16;
constexpr int      BLK    = 256;
constexpr uint32_t MASK19 = (1u << 19) - 1u;
constexpr uint32_t P1     = 2654435761u;
constexpr uint32_t P2     = 805459861u;

// RES[l] = floor(16 * (2^(1/3))^l)
__device__ __constant__ float RES_C[LVL] = {
    16.f, 20.f, 25.f, 32.f, 40.f, 50.f, 64.f, 80.f,
    101.f, 128.f, 161.f, 203.f, 256.f, 322.f, 406.f, 512.f
};

// Dense (de-hashed) tables for the two coarsest levels.
constexpr int D0 = 17;              // res 16 -> grid coords 0..16
constexpr int D1 = 21;              // res 20 -> grid coords 0..20
constexpr int N0 = D0 * D0 * D0;    // 4913  (39.3 KB as float2)
constexpr int N1 = D1 * D1 * D1;    // 9261  (74.1 KB as float2)
__device__ float2 g_dense0[N0];
__device__ float2 g_dense1[N1];

__global__ void build_dense_kernel(const float* __restrict__ tables)
{
    int t = blockIdx.x * blockDim.x + threadIdx.x;
    const float2* tbl = reinterpret_cast<const float2*>(tables);
    if (t < N0) {
        int k = t % D0, j = (t / D0) % D0, i = t / (D0 * D0);
        uint32_t h = ((uint32_t)i ^ ((uint32_t)j * P1) ^ ((uint32_t)k * P2)) & MASK19;
        g_dense0[t] = tbl[h];                      // level 0 base
    } else if (t < N0 + N1) {
        int u = t - N0;
        int k = u % D1, j = (u / D1) % D1, i = u / (D1 * D1);
        uint32_t h = ((uint32_t)i ^ ((uint32_t)j * P1) ^ ((uint32_t)k * P2)) & MASK19;
        g_dense1[u] = tbl[(1u << 19) + h];         // level 1 base
    }
}

// Fetch a corner pair (entries ia, ib). If adj, ib == ia^1 and both live in
// one aligned 16B chunk -> single LDG.128 (one 32B sector). Otherwise a
// predicated second LDG.64 fetches ib.
__device__ __forceinline__ void gather_pair(const float2* __restrict__ tbl,
                                            uint32_t ia, uint32_t ib, bool adj,
                                            float2& ca, float2& cb)
{
    const float4* __restrict__ t4 = reinterpret_cast<const float4*>(tbl);
    float4 qa = __ldg(&t4[ia >> 1]);
    float2 lo = make_float2(qa.x, qa.y);
    float2 hi = make_float2(qa.z, qa.w);
    ca = (ia & 1u) ? hi : lo;
    if (adj) {
        cb = (ia & 1u) ? lo : hi;
    } else {
        cb = __ldg(&tbl[ib]);
    }
}

__global__ __launch_bounds__(BLK)
void ngp_enc_kernel(const float* __restrict__ x,
                    const float* __restrict__ tables,
                    float* __restrict__ out,
                    int B)
{
    int b = blockIdx.x * BLK + threadIdx.x;
    if (b >= B) return;

    const float x0 = x[3 * b + 0];
    const float x1 = x[3 * b + 1];
    const float x2 = x[3 * b + 2];

    float acc[2 * LVL];

    // ---- Levels 0,1: dense tables (L1-resident), pair along dim2 ----
    #pragma unroll
    for (int l = 0; l < 2; ++l) {
        const int D = (l == 0) ? D0 : D1;
        const float2* __restrict__ dt = (l == 0) ? g_dense0 : g_dense1;
        const float r = RES_C[l];
        const float s0 = x0 * r, s1 = x1 * r, s2 = x2 * r;
        const float f0 = floorf(s0), f1 = floorf(s1), f2 = floorf(s2);
        const float fr0 = s0 - f0, fr1 = s1 - f1, fr2 = s2 - f2;
        const uint32_t g0 = (uint32_t)f0, g1 = (uint32_t)f1, g2 = (uint32_t)f2;

        const float w0a = 1.f - fr0, w0b = fr0;
        const float w1a = 1.f - fr1, w1b = fr1;
        const float w2a = 1.f - fr2, w2b = fr2;

        float a0 = 0.f, a1 = 0.f;
        #pragma unroll
        for (int p = 0; p < 4; ++p) {
            const uint32_t bi = p & 1, bj = (p >> 1) & 1;
            const uint32_t ia = ((g0 + bi) * D + (g1 + bj)) * D + g2;
            const uint32_t ib = ia + 1u;
            const bool adj = (ia & 1u) == 0u;
            float2 ca, cb;
            gather_pair(dt, ia, ib, adj, ca, cb);
            const float w01 = (bi ? w0b : w0a) * (bj ? w1b : w1a);
            const float wa = w01 * w2a, wb = w01 * w2b;
            a0 = fmaf(wa, ca.x, a0); a1 = fmaf(wa, ca.y, a1);
            a0 = fmaf(wb, cb.x, a0); a1 = fmaf(wb, cb.y, a1);
        }
        acc[2 * l + 0] = a0;
        acc[2 * l + 1] = a1;
    }

    // ---- Levels 2..15: hashed tables, pair along dim0 (prime = 1) ----
    #pragma unroll
    for (int l = 2; l < LVL; ++l) {
        const float r = RES_C[l];
        const float s0 = x0 * r, s1 = x1 * r, s2 = x2 * r;
        const float f0 = floorf(s0), f1 = floorf(s1), f2 = floorf(s2);
        const float fr0 = s0 - f0, fr1 = s1 - f1, fr2 = s2 - f2;
        const uint32_t g0 = (uint32_t)f0, g1 = (uint32_t)f1, g2 = (uint32_t)f2;

        const uint32_t h1a = g1 * P1, h1b = h1a + P1;
        const uint32_t h2a = g2 * P2, h2b = h2a + P2;
        const bool adj = (g0 & 1u) == 0u;   // g0+1 == g0^1

        const float2* __restrict__ tbl =
            reinterpret_cast<const float2*>(tables) + ((size_t)l << 19);

        const float w0a = 1.f - fr0, w0b = fr0;
        const float w1a = 1.f - fr1, w1b = fr1;
        const float w2a = 1.f - fr2, w2b = fr2;

        float a0 = 0.f, a1 = 0.f;
        #pragma unroll
        for (int p = 0; p < 4; ++p) {
            const uint32_t m = ((p & 1) ? h1b : h1a) ^ ((p & 2) ? h2b : h2a);
            const uint32_t ia = (g0 ^ m) & MASK19;
            const uint32_t ib = ((g0 + 1u) ^ m) & MASK19;
            float2 ca, cb;
            gather_pair(tbl, ia, ib, adj, ca, cb);
            const float w12 = ((p & 1) ? w1b : w1a) * ((p & 2) ? w2b : w2a);
            const float wa = w12 * w0a, wb = w12 * w0b;
            a0 = fmaf(wa, ca.x, a0); a1 = fmaf(wa, ca.y, a1);
            a0 = fmaf(wb, cb.x, a0); a1 = fmaf(wb, cb.y, a1);
        }
        acc[2 * l + 0] = a0;
        acc[2 * l + 1] = a1;
    }

    // 32 contiguous floats per point -> 8 x STG.128
    float4* o = reinterpret_cast<float4*>(out + (size_t)b * (2 * LVL));
    #pragma unroll
    for (int i = 0; i < 2 * LVL / 4; ++i) {
        o[i] = make_float4(acc[4 * i + 0], acc[4 * i + 1],
                           acc[4 * i + 2], acc[4 * i + 3]);
    }
}

extern "C" void kernel_launch(void* const* d_in, const int* in_sizes, int n_in,
                              void* d_out, int out_size)
{
    const float* x      = (const float*)d_in[0];
    const float* tables = (const float*)d_in[1];
    float* out          = (float*)d_out;

    const int B = in_sizes[0] / 3;

    const int nDense = N0 + N1;
    build_dense_kernel<<<(nDense + 255) / 256, 256>>>(tables);

    const int grid = (B + BLK - 1) / BLK;
    ngp_enc_kernel<<<grid, BLK>>>(x, tables, out, B);
}

// round 10
// speedup vs baseline: 1.3862x; 1.3862x over previous
#include <cuda_runtime.h>
#include <cstdint>

// NGP hash-grid interpolation encoding.
// B=262144 points (x in [0,1)^3), L=16 levels, T=19 (2^19 entries), F=2.
//
// R6: pure scattered LDG.64 gathers (uniform control flow — fastest measured
// shape), with levels processed in groups of 4 so only 8 accumulator floats
// are live at a time (register diet -> higher occupancy -> saturate L1tex).

constexpr int      LVL    = 16;
constexpr int      BLK    = 256;
constexpr uint32_t MASK19 = (1u << 19) - 1u;
constexpr uint32_t P1     = 2654435761u;
constexpr uint32_t P2     = 805459861u;

// RES[l] = floor(16 * (2^(1/3))^l)
__device__ __constant__ float RES_C[LVL] = {
    16.f, 20.f, 25.f, 32.f, 40.f, 50.f, 64.f, 80.f,
    101.f, 128.f, 161.f, 203.f, 256.f, 322.f, 406.f, 512.f
};

__global__ __launch_bounds__(BLK)
void ngp_enc_kernel(const float* __restrict__ x,
                    const float* __restrict__ tables,
                    float* __restrict__ out,
                    int B)
{
    int b = blockIdx.x * BLK + threadIdx.x;
    if (b >= B) return;

    const float x0 = x[3 * b + 0];
    const float x1 = x[3 * b + 1];
    const float x2 = x[3 * b + 2];

    float4* o = reinterpret_cast<float4*>(out + (size_t)b * (2 * LVL));

    // Process 4 levels per group: 32 independent LDG.64 in flight per group,
    // only 8 accumulator floats live, stored immediately as 2x STG.128.
    #pragma unroll
    for (int g = 0; g < LVL / 4; ++g) {
        float acc[8];

        #pragma unroll
        for (int li = 0; li < 4; ++li) {
            const int l = g * 4 + li;
            const float r = RES_C[l];
            const float s0 = x0 * r, s1 = x1 * r, s2 = x2 * r;
            const float f0 = floorf(s0), f1 = floorf(s1), f2 = floorf(s2);
            const float fr0 = s0 - f0, fr1 = s1 - f1, fr2 = s2 - f2;
            const uint32_t g0 = (uint32_t)f0;
            const uint32_t g1 = (uint32_t)f1;
            const uint32_t g2 = (uint32_t)f2;

            const uint32_t h0a = g0,        h0b = g0 + 1u;   // prime = 1
            const uint32_t h1a = g1 * P1,   h1b = h1a + P1;
            const uint32_t h2a = g2 * P2,   h2b = h2a + P2;

            const float2* __restrict__ tbl =
                reinterpret_cast<const float2*>(tables) + ((size_t)l << 19);

            uint32_t idx[8];
            #pragma unroll
            for (int v = 0; v < 8; ++v) {
                uint32_t h = ((v & 1) ? h0b : h0a)
                           ^ ((v & 2) ? h1b : h1a)
                           ^ ((v & 4) ? h2b : h2a);
                idx[v] = h & MASK19;
            }

            float2 t[8];
            #pragma unroll
            for (int v = 0; v < 8; ++v) {
                t[v] = __ldg(&tbl[idx[v]]);
            }

            const float w0a = 1.0f - fr0, w0b = fr0;
            const float w1a = 1.0f - fr1, w1b = fr1;
            const float w2a = 1.0f - fr2, w2b = fr2;

            float a0 = 0.0f, a1 = 0.0f;
            #pragma unroll
            for (int v = 0; v < 8; ++v) {
                float w = (((v & 1) ? w0b : w0a) * ((v & 2) ? w1b : w1a))
                        * ((v & 4) ? w2b : w2a);
                a0 = fmaf(w, t[v].x, a0);
                a1 = fmaf(w, t[v].y, a1);
            }
            acc[2 * li + 0] = a0;
            acc[2 * li + 1] = a1;
        }

        // 8 contiguous floats -> 2x STG.128 (same stores as before, earlier).
        o[2 * g + 0] = make_float4(acc[0], acc[1], acc[2], acc[3]);
        o[2 * g + 1] = make_float4(acc[4], acc[5], acc[6], acc[7]);
    }
}

extern "C" void kernel_launch(void* const* d_in, const int* in_sizes, int n_in,
                              void* d_out, int out_size)
{
    const float* x      = (const float*)d_in[0];
    const float* tables = (const float*)d_in[1];
    float* out          = (float*)d_out;

    const int B = in_sizes[0] / 3;
    const int grid = (B + BLK - 1) / BLK;
    ngp_enc_kernel<<<grid, BLK>>>(x, tables, out, B);
}

// round 13
// speedup vs baseline: 1.9293x; 1.3918x over previous
#include <cuda_runtime.h>
#include <cstdint>

// NGP hash-grid interpolation encoding.
// B=262144 points, L=16 levels, T=2^19 entries, F=2.
//
// R11: cooperative pair-lane layout. Two adjacent lanes handle one point;
// lane parity p is the dim0 corner border. For even g0 the pair's table
// indices differ only in bit 0 -> both 8B entries in one 32B sector -> the
// coalescer merges the two lanes of each LDG.64 into ONE L1tex wavefront.
// Uniform control flow, no wide loads, no divergence (fixes R5's mistake).

constexpr int      LVL    = 16;
constexpr int      BLK    = 256;
constexpr uint32_t MASK19 = (1u << 19) - 1u;
constexpr uint32_t P1     = 2654435761u;
constexpr uint32_t P2     = 805459861u;

// RES[l] = floor(16 * (2^(1/3))^l)
__device__ __constant__ float RES_C[LVL] = {
    16.f, 20.f, 25.f, 32.f, 40.f, 50.f, 64.f, 80.f,
    101.f, 128.f, 161.f, 203.f, 256.f, 322.f, 406.f, 512.f
};

__global__ __launch_bounds__(BLK)
void ngp_enc_kernel(const float* __restrict__ x,
                    const float* __restrict__ tables,
                    float* __restrict__ out,
                    int B)
{
    const int t = blockIdx.x * BLK + threadIdx.x;
    const int b = t >> 1;          // point id (2 lanes per point)
    const int p = t & 1;           // dim0 corner border for this lane
    if (b >= B) return;            // never triggers for B=262144 (grid exact)

    const float x0 = x[3 * b + 0];
    const float x1 = x[3 * b + 1];
    const float x2 = x[3 * b + 2];

    // Each lane keeps the results of 8 levels: lane p owns levels [8p, 8p+8).
    float keep[16];

    #pragma unroll
    for (int l = 0; l < LVL; ++l) {
        const float r = RES_C[l];
        const float s0 = x0 * r, s1 = x1 * r, s2 = x2 * r;
        const float f0 = floorf(s0), f1 = floorf(s1), f2 = floorf(s2);
        const float fr0 = s0 - f0, fr1 = s1 - f1, fr2 = s2 - f2;
        const uint32_t g0 = (uint32_t)f0;
        const uint32_t g1 = (uint32_t)f1;
        const uint32_t g2 = (uint32_t)f2;

        // This lane's dim0 hash contribution (prime = 1).
        const uint32_t h0  = g0 + (uint32_t)p;
        const uint32_t h1a = g1 * P1, h1b = h1a + P1;
        const uint32_t h2a = g2 * P2, h2b = h2a + P2;

        const uint32_t i0 = (h0 ^ h1a ^ h2a) & MASK19;
        const uint32_t i1 = (h0 ^ h1b ^ h2a) & MASK19;
        const uint32_t i2 = (h0 ^ h1a ^ h2b) & MASK19;
        const uint32_t i3 = (h0 ^ h1b ^ h2b) & MASK19;

        const float2* __restrict__ tbl =
            reinterpret_cast<const float2*>(tables) + ((size_t)l << 19);

        // 4 LDG.64 per lane; paired lanes coalesce into shared sectors when
        // g0 is even (50% of cells) -> ~25% fewer L1tex wavefronts.
        const float2 t0 = __ldg(&tbl[i0]);
        const float2 t1 = __ldg(&tbl[i1]);
        const float2 t2 = __ldg(&tbl[i2]);
        const float2 t3 = __ldg(&tbl[i3]);

        const float w1a = 1.0f - fr1, w1b = fr1;
        const float w2a = 1.0f - fr2, w2b = fr2;
        const float w00 = w1a * w2a;
        const float w01 = w1b * w2a;
        const float w10 = w1a * w2b;
        const float w11 = w1b * w2b;

        // Partial sum over this lane's 4 corners, scaled by the dim0 weight.
        float a0 = fmaf(w00, t0.x, fmaf(w01, t1.x, fmaf(w10, t2.x, w11 * t3.x)));
        float a1 = fmaf(w00, t0.y, fmaf(w01, t1.y, fmaf(w10, t2.y, w11 * t3.y)));
        const float w0 = p ? fr0 : (1.0f - fr0);
        a0 *= w0;
        a1 *= w0;

        // Combine the two half-sums across the lane pair.
        a0 += __shfl_xor_sync(0xFFFFFFFFu, a0, 1);
        a1 += __shfl_xor_sync(0xFFFFFFFFu, a1, 1);

        // Lane (l>>3) retains this level's result.
        if ((l >> 3) == p) {
            keep[2 * (l & 7) + 0] = a0;
            keep[2 * (l & 7) + 1] = a1;
        }
    }

    // Lane p stores floats [16p, 16p+16) of the point's 32-float output.
    // Across the warp this is 16 points x 128B fully contiguous.
    float4* o = reinterpret_cast<float4*>(out + (size_t)b * (2 * LVL) + p * 16);
    o[0] = make_float4(keep[0],  keep[1],  keep[2],  keep[3]);
    o[1] = make_float4(keep[4],  keep[5],  keep[6],  keep[7]);
    o[2] = make_float4(keep[8],  keep[9],  keep[10], keep[11]);
    o[3] = make_float4(keep[12], keep[13], keep[14], keep[15]);
}

extern "C" void kernel_launch(void* const* d_in, const int* in_sizes, int n_in,
                              void* d_out, int out_size)
{
    const float* x      = (const float*)d_in[0];
    const float* tables = (const float*)d_in[1];
    float* out          = (float*)d_out;

    const int B = in_sizes[0] / 3;
    const int nThreads = 2 * B;                    // 2 lanes per point
    const int grid = (nThreads + BLK - 1) / BLK;
    ngp_enc_kernel<<<grid, BLK>>>(x, tables, out, B);
}